// round 16
// baseline (speedup 1.0000x reference)
#include <cuda_runtime.h>
#include <cstdint>

#define BATCH 32
#define NPTS  65536
#define SSAMP 512
#define CPB   4                 // CTAs per batch = cluster size
#define PSH   (NPTS / CPB)      // 16384 points per CTA shard
#define TPB   512
#define NWARP (TPB / 32)        // 16 warps
#define NSLOT (CPB * NWARP)     // 64 candidate slots per parity
#define PAIRS (PSH / (2 * TPB)) // 16 point-pairs per thread
#define PFP   8                 // pairs prefetched into regs during the wait
#define PPT   (2 * PAIRS)       // 32 points per thread

__device__ int g_idx[BATCH][SSAMP];

// ---- packed f32x2 helpers (IEEE-identical to scalar ops) ----
#define ADD_F32X2(out, a, b) \
    asm("add.rn.f32x2 %0, %1, %2;" : "=l"(out) : "l"(a), "l"(b))
#define MUL_F32X2(out, a, b) \
    asm("mul.rn.f32x2 %0, %1, %2;" : "=l"(out) : "l"(a), "l"(b))
#define FMA_F32X2(out, a, b, c) \
    asm("fma.rn.f32x2 %0, %1, %2, %3;" : "=l"(out) : "l"(a), "l"(b), "l"(c))
#define PACK_F32X2(out, lo, hi) \
    asm("mov.b64 %0, {%1, %2};" : "=l"(out) : "r"(lo), "r"(hi))
#define UNPACK_F32X2(lo, hi, in) \
    asm("mov.b64 {%0, %1}, %2;" : "=r"(lo), "=r"(hi) : "l"(in))

#define REDUX_MAX_U32(out, in) \
    asm("redux.sync.max.u32 %0, %1, 0xffffffff;" : "=r"(out) : "r"(in))

// R15 winner (856us: prefetch-under-tail) + (a) mask/ffs locate (32
// independent compares instead of a 32-deep serial SEL chain) and
// (b) mapa hoisted out of the loop.
__global__ void __launch_bounds__(TPB, 1) __cluster_dims__(CPB, 1, 1)
fps_kernel(const float* __restrict__ xyz) {
    extern __shared__ char smem_raw[];
    ulonglong2* xyp = (ulonglong2*)smem_raw;
    float* zs = (float*)(xyp + PSH / 2);
    unsigned long long* keys = (unsigned long long*)(zs + PSH);      // [2][64]
    float4* coord = (float4*)(keys + 2 * NSLOT);                     // [2][64]
    unsigned long long* mbar = (unsigned long long*)(coord + 2 * NSLOT);

    const int cta  = blockIdx.x;
    const int b    = cta >> 2;          // batch
    const int c    = cta & 3;           // rank in cluster
    const int base = c * PSH;
    const int t    = threadIdx.x;
    const int w    = t >> 5;
    const int lane = t & 31;
    const float* X = xyz + (size_t)b * NPTS * 3;

    // Load shard, deinterleave [P,3] -> {xy-pairs, z} (coalesced, one-time).
    float* xyf = (float*)xyp;
    for (int i = t; i < 3 * PSH; i += TPB) {
        float v = X[(size_t)base * 3 + i];
        int p = i / 3;
        int k = i - 3 * p;
        if (k == 2) zs[p] = v;
        else        xyf[(p >> 1) * 4 + k * 2 + (p & 1)] = v;
    }

    uint32_t keys_base  = (uint32_t)__cvta_generic_to_shared(keys);
    uint32_t coord_base = (uint32_t)__cvta_generic_to_shared(coord);
    uint32_t mbar_base  = (uint32_t)__cvta_generic_to_shared(mbar);
    if (t == 0) {
        asm volatile("mbarrier.init.shared.b64 [%0], %1;"
                     :: "r"(mbar_base), "r"((unsigned)NSLOT) : "memory");
        asm volatile("mbarrier.init.shared.b64 [%0], %1;"
                     :: "r"(mbar_base + 8), "r"((unsigned)NSLOT) : "memory");
    }
    __syncthreads();
    asm volatile("barrier.cluster.arrive.aligned;" ::: "memory");
    asm volatile("barrier.cluster.wait.aligned;" ::: "memory");

    const unsigned long long* zs2 = (const unsigned long long*)zs;

    // prefetch buffer: pairs [0, PFP) of the upcoming scan
    ulonglong2 pfxy[PFP];
    unsigned long long pfz[PFP];
#pragma unroll
    for (int j = 0; j < PFP; j++) {
        int q = t + j * TPB;
        pfxy[j] = xyp[q]; pfz[j] = zs2[q];
    }

    float dist[PPT];
#pragma unroll
    for (int j = 0; j < PPT; j++) dist[j] = 1e10f;

    float cx = X[0], cy = X[1], cz = X[2];   // first centroid = point 0
    if (c == 0 && t == 0) g_idx[b][0] = 0;

    const int slot = c * NWARP + w;          // this warp's global slot

    // Hoisted remote addresses (lanes 0-3 send to rank=lane), per parity.
    uint32_t rka[2], rca[2], rma[2];
    if (lane < CPB) {
#pragma unroll
        for (int p2 = 0; p2 < 2; p2++) {
            uint32_t kaddr = keys_base + (uint32_t)(p2 * NSLOT + slot) * 8u;
            uint32_t caddr = coord_base + (uint32_t)(p2 * NSLOT + slot) * 16u;
            uint32_t mb    = mbar_base + (uint32_t)p2 * 8u;
            asm("mapa.shared::cluster.u32 %0, %1, %2;" : "=r"(rka[p2]) : "r"(kaddr), "r"(lane));
            asm("mapa.shared::cluster.u32 %0, %1, %2;" : "=r"(rca[p2]) : "r"(caddr), "r"(lane));
            asm("mapa.shared::cluster.u32 %0, %1, %2;" : "=r"(rma[p2]) : "r"(mb),    "r"(lane));
        }
    }

    for (int iter = 0; iter < SSAMP - 1; iter++) {
        const int par = iter & 1;
        const unsigned ph = (unsigned)((iter >> 1) & 1);
        unsigned long long ncx2, ncy2, ncz2;
        {
            uint32_t nx = __float_as_uint(-cx);
            uint32_t ny = __float_as_uint(-cy);
            uint32_t nz = __float_as_uint(-cz);
            PACK_F32X2(ncx2, nx, nx);
            PACK_F32X2(ncy2, ny, ny);
            PACK_F32X2(ncz2, nz, nz);
        }

        // --- scan: pairs 0..7 from prefetch regs, 8..15 from SMEM ---
        float b0 = -1.0f, b1 = -1.0f, b2m = -1.0f, b3m = -1.0f;
#pragma unroll
        for (int jj = 0; jj < PAIRS; jj++) {
            unsigned long long x2, y2, z2;
            if (jj < PFP) {
                x2 = pfxy[jj].x; y2 = pfxy[jj].y; z2 = pfz[jj];
            } else {
                int q = t + jj * TPB;
                ulonglong2 xy = xyp[q];          // LDS.128
                x2 = xy.x; y2 = xy.y; z2 = zs2[q];
            }
            unsigned long long dx2, dy2, dz2, s2;
            ADD_F32X2(dx2, x2, ncx2);
            ADD_F32X2(dy2, y2, ncy2);
            ADD_F32X2(dz2, z2, ncz2);
            MUL_F32X2(s2, dx2, dx2);
            FMA_F32X2(s2, dy2, dy2, s2);
            FMA_F32X2(s2, dz2, dz2, s2);
            uint32_t lo, hi;
            UNPACK_F32X2(lo, hi, s2);
            float v0 = fminf(dist[2 * jj],     __uint_as_float(lo));
            float v1 = fminf(dist[2 * jj + 1], __uint_as_float(hi));
            dist[2 * jj]     = v0;
            dist[2 * jj + 1] = v1;
            if (jj & 1) { b2m = fmaxf(b2m, v0); b3m = fmaxf(b3m, v1); }
            else        { b0  = fmaxf(b0,  v0); b1  = fmaxf(b1,  v1); }
        }
        float bv = fmaxf(fmaxf(b0, b1), fmaxf(b2m, b3m));

        // issue next iteration's prefetch NOW — latency hides under the
        // locate, the send, and the mbarrier wait below.
#pragma unroll
        for (int j = 0; j < PFP; j++) {
            int q = t + j * TPB;
            pfxy[j] = xyp[q]; pfz[j] = zs2[q];
        }

        // locate smallest k with dist[k]==bv: independent compares -> ffs.
        // p(k) = 2(t + (k>>1)*TPB) + (k&1) is monotone in k.
        unsigned m0 = 0, m1 = 0;
#pragma unroll
        for (int k = 0; k < 16; k++)
            m0 |= (dist[k] == bv) ? (1u << k) : 0u;
#pragma unroll
        for (int k = 16; k < 32; k++)
            m1 |= (dist[k] == bv) ? (1u << (k - 16)) : 0u;
        int k0 = m0 ? (__ffs(m0) - 1) : (__ffs(m1) + 15);
        int bp = 2 * (t + (k0 >> 1) * TPB) + (k0 & 1);

        // warp-level exact argmax via two redux (hi = dist bits, lo = ~idx)
        unsigned khi = __float_as_uint(bv);
        unsigned klo = ~(unsigned)(base + bp);
        unsigned H, L;
        REDUX_MAX_U32(H, khi);
        unsigned cand = (khi == H) ? klo : 0u;
        REDUX_MAX_U32(L, cand);
        unsigned long long wkey = ((unsigned long long)H << 32) | L;

        // lanes 0-3: send warp candidate to rank=lane, arrive remote mbar
        {
            int off = (int)(~L) - base;           // in [0, PSH)
            if (lane < CPB) {
                float wx = xyf[(off >> 1) * 4 + (off & 1)];
                float wy = xyf[(off >> 1) * 4 + 2 + (off & 1)];
                float wz = zs[off];
                unsigned long long xy;
                PACK_F32X2(xy, __float_as_uint(wx), __float_as_uint(wy));
                asm volatile("st.shared::cluster.u64 [%0], %1;"
                             :: "r"(rka[par]), "l"(wkey) : "memory");
                asm volatile("st.shared::cluster.u64 [%0], %1;"
                             :: "r"(rca[par]), "l"(xy) : "memory");
                asm volatile("st.shared::cluster.u32 [%0+8], %1;"
                             :: "r"(rca[par]), "r"(__float_as_uint(wz)) : "memory");
                asm volatile(
                    "mbarrier.arrive.release.cluster.shared::cluster.b64 _, [%0];"
                    :: "r"(rma[par]) : "memory");
            }
        }

        // wait on LOCAL parity mbarrier (acquire, cluster scope) — hot poll
        {
            uint32_t mb = mbar_base + (uint32_t)par * 8u;
            uint32_t done;
            do {
                asm volatile(
                    "{\n\t.reg .pred p;\n\t"
                    "mbarrier.try_wait.parity.acquire.cluster.shared::cta.b64 p, [%1], %2;\n\t"
                    "selp.b32 %0, 1, 0, p;\n\t}"
                    : "=r"(done) : "r"(mb), "r"(ph) : "memory");
            } while (!done);
        }

        // every warp redundantly reduces the 64 candidates
        {
            const ulonglong2* kk2 = (const ulonglong2*)(keys + par * NSLOT);
            ulonglong2 kk = kk2[lane];            // slots 2*lane, 2*lane+1
            unsigned long long km = (kk.x > kk.y) ? kk.x : kk.y;
            unsigned hi = (unsigned)(km >> 32), lo = (unsigned)km;
            unsigned Hg, Lg;
            REDUX_MAX_U32(Hg, hi);
            unsigned cnd = (hi == Hg) ? lo : 0u;
            REDUX_MAX_U32(Lg, cnd);
            unsigned long long W = ((unsigned long long)Hg << 32) | Lg;
            unsigned bal = __ballot_sync(0xffffffffu, km == W);
            int src = __ffs(bal) - 1;
            int sidx = (kk.x == W) ? (2 * lane) : (2 * lane + 1);
            sidx = __shfl_sync(0xffffffffu, sidx, src);
            float4 cc = coord[par * NSLOT + sidx]; // broadcast LDS.128
            cx = cc.x; cy = cc.y; cz = cc.z;
            if (c == 0 && t == 0)
                g_idx[b][iter + 1] = (int)(~Lg);
        }
    }
}

// Gather: out = [B,S,3] xyz_sampled then [B,S,64] f_sampled. float4 copies.
__global__ void gather_kernel(const float* __restrict__ xyz,
                              const float* __restrict__ f,
                              float* __restrict__ out) {
    int r    = blockIdx.x * 16 + (threadIdx.x >> 4);  // row 0 .. B*S-1
    int lane = threadIdx.x & 15;
    int b = r >> 9;
    int j = r & (SSAMP - 1);
    int idx = g_idx[b][j];
    const float4* fr = (const float4*)(f + ((size_t)b * NPTS + idx) * 64);
    float4* fo = (float4*)(out + (size_t)BATCH * SSAMP * 3 +
                           ((size_t)b * SSAMP + j) * 64);
    fo[lane] = fr[lane];
    if (lane < 3) {
        out[((size_t)b * SSAMP + j) * 3 + lane] =
            xyz[((size_t)b * NPTS + idx) * 3 + lane];
    }
}

extern "C" void kernel_launch(void* const* d_in, const int* in_sizes, int n_in,
                              void* d_out, int out_size) {
    const float* xyz = (const float*)d_in[0];
    const float* f   = (const float*)d_in[1];
    float* out = (float*)d_out;

    size_t smem = (PSH / 2) * sizeof(ulonglong2)
                + PSH * sizeof(float)
                + 2 * NSLOT * sizeof(unsigned long long)
                + 2 * NSLOT * sizeof(float4)
                + 2 * sizeof(unsigned long long);
    cudaFuncSetAttribute(fps_kernel,
                         cudaFuncAttributeMaxDynamicSharedMemorySize, (int)smem);

    fps_kernel<<<BATCH * CPB, TPB, smem>>>(xyz);
    gather_kernel<<<(BATCH * SSAMP) / 16, 256>>>(xyz, f, out);
}

// round 17
// speedup vs baseline: 1.0640x; 1.0640x over previous
#include <cuda_runtime.h>
#include <cstdint>

#define BATCH 32
#define NPTS  65536
#define SSAMP 512
#define CPB   4                 // CTAs per batch = cluster size
#define PSH   (NPTS / CPB)      // 16384 points per CTA shard
#define TPB   512
#define NWARP (TPB / 32)        // 16 warps
#define NSLOT (CPB * NWARP)     // 64 candidate slots per parity
#define PAIRS (PSH / (2 * TPB)) // 16 point-pairs per thread
#define PFP   8                 // pairs prefetched into regs during the wait
#define PPT   (2 * PAIRS)       // 32 points per thread

// ---- packed f32x2 helpers (IEEE-identical to scalar ops) ----
#define ADD_F32X2(out, a, b) \
    asm("add.rn.f32x2 %0, %1, %2;" : "=l"(out) : "l"(a), "l"(b))
#define MUL_F32X2(out, a, b) \
    asm("mul.rn.f32x2 %0, %1, %2;" : "=l"(out) : "l"(a), "l"(b))
#define FMA_F32X2(out, a, b, c) \
    asm("fma.rn.f32x2 %0, %1, %2, %3;" : "=l"(out) : "l"(a), "l"(b), "l"(c))
#define PACK_F32X2(out, lo, hi) \
    asm("mov.b64 %0, {%1, %2};" : "=l"(out) : "r"(lo), "r"(hi))
#define UNPACK_F32X2(lo, hi, in) \
    asm("mov.b64 {%0, %1}, %2;" : "=r"(lo), "=r"(hi) : "l"(in))

#define REDUX_MAX_U32(out, in) \
    asm("redux.sync.max.u32 %0, %1, 0xffffffff;" : "=r"(out) : "r"(in))

// Exact R15 body (856us: prefetch-under-tail, serial locate, per-iter mapa)
// + FUSED GATHER: every CTA records the winning index each iteration in its
// own SMEM; at loop end the 4 cluster CTAs cooperatively write their batch's
// [512,3] xyz and [512,64] f output rows. No second kernel.
__global__ void __launch_bounds__(TPB, 1) __cluster_dims__(CPB, 1, 1)
fps_kernel(const float* __restrict__ xyz,
           const float* __restrict__ f,
           float* __restrict__ out) {
    extern __shared__ char smem_raw[];
    ulonglong2* xyp = (ulonglong2*)smem_raw;
    float* zs = (float*)(xyp + PSH / 2);
    unsigned long long* keys = (unsigned long long*)(zs + PSH);      // [2][64]
    float4* coord = (float4*)(keys + 2 * NSLOT);                     // [2][64]
    unsigned long long* mbar = (unsigned long long*)(coord + 2 * NSLOT);
    int* sidx = (int*)(mbar + 2);                                    // [512]

    const int cta  = blockIdx.x;
    const int b    = cta >> 2;          // batch
    const int c    = cta & 3;           // rank in cluster
    const int base = c * PSH;
    const int t    = threadIdx.x;
    const int w    = t >> 5;
    const int lane = t & 31;
    const float* X = xyz + (size_t)b * NPTS * 3;

    // Load shard, deinterleave [P,3] -> {xy-pairs, z} (coalesced, one-time).
    float* xyf = (float*)xyp;
    for (int i = t; i < 3 * PSH; i += TPB) {
        float v = X[(size_t)base * 3 + i];
        int p = i / 3;
        int k = i - 3 * p;
        if (k == 2) zs[p] = v;
        else        xyf[(p >> 1) * 4 + k * 2 + (p & 1)] = v;
    }

    uint32_t keys_base  = (uint32_t)__cvta_generic_to_shared(keys);
    uint32_t coord_base = (uint32_t)__cvta_generic_to_shared(coord);
    uint32_t mbar_base  = (uint32_t)__cvta_generic_to_shared(mbar);
    if (t == 0) {
        asm volatile("mbarrier.init.shared.b64 [%0], %1;"
                     :: "r"(mbar_base), "r"((unsigned)NSLOT) : "memory");
        asm volatile("mbarrier.init.shared.b64 [%0], %1;"
                     :: "r"(mbar_base + 8), "r"((unsigned)NSLOT) : "memory");
        sidx[0] = 0;
    }
    __syncthreads();
    asm volatile("barrier.cluster.arrive.aligned;" ::: "memory");
    asm volatile("barrier.cluster.wait.aligned;" ::: "memory");

    const unsigned long long* zs2 = (const unsigned long long*)zs;

    // prefetch buffer: pairs [0, PFP) of the upcoming scan
    ulonglong2 pfxy[PFP];
    unsigned long long pfz[PFP];
#pragma unroll
    for (int j = 0; j < PFP; j++) {
        int q = t + j * TPB;
        pfxy[j] = xyp[q]; pfz[j] = zs2[q];
    }

    float dist[PPT];
#pragma unroll
    for (int j = 0; j < PPT; j++) dist[j] = 1e10f;

    float cx = X[0], cy = X[1], cz = X[2];   // first centroid = point 0

    const int slot = c * NWARP + w;          // this warp's global slot

    for (int iter = 0; iter < SSAMP - 1; iter++) {
        const int par = iter & 1;
        const unsigned ph = (unsigned)((iter >> 1) & 1);
        unsigned long long ncx2, ncy2, ncz2;
        {
            uint32_t nx = __float_as_uint(-cx);
            uint32_t ny = __float_as_uint(-cy);
            uint32_t nz = __float_as_uint(-cz);
            PACK_F32X2(ncx2, nx, nx);
            PACK_F32X2(ncy2, ny, ny);
            PACK_F32X2(ncz2, nz, nz);
        }

        // --- scan: pairs 0..7 from prefetch regs, 8..15 from SMEM ---
        float b0 = -1.0f, b1 = -1.0f, b2m = -1.0f, b3m = -1.0f;
#pragma unroll
        for (int jj = 0; jj < PAIRS; jj++) {
            unsigned long long x2, y2, z2;
            if (jj < PFP) {
                x2 = pfxy[jj].x; y2 = pfxy[jj].y; z2 = pfz[jj];
            } else {
                int q = t + jj * TPB;
                ulonglong2 xy = xyp[q];          // LDS.128
                x2 = xy.x; y2 = xy.y; z2 = zs2[q];
            }
            unsigned long long dx2, dy2, dz2, s2;
            ADD_F32X2(dx2, x2, ncx2);
            ADD_F32X2(dy2, y2, ncy2);
            ADD_F32X2(dz2, z2, ncz2);
            MUL_F32X2(s2, dx2, dx2);
            FMA_F32X2(s2, dy2, dy2, s2);
            FMA_F32X2(s2, dz2, dz2, s2);
            uint32_t lo, hi;
            UNPACK_F32X2(lo, hi, s2);
            float v0 = fminf(dist[2 * jj],     __uint_as_float(lo));
            float v1 = fminf(dist[2 * jj + 1], __uint_as_float(hi));
            dist[2 * jj]     = v0;
            dist[2 * jj + 1] = v1;
            if (jj & 1) { b2m = fmaxf(b2m, v0); b3m = fmaxf(b3m, v1); }
            else        { b0  = fmaxf(b0,  v0); b1  = fmaxf(b1,  v1); }
        }
        float bv = fmaxf(fmaxf(b0, b1), fmaxf(b2m, b3m));

        // issue next iteration's prefetch NOW — latency hides under the
        // locate, the send, and the mbarrier wait below.
#pragma unroll
        for (int j = 0; j < PFP; j++) {
            int q = t + j * TPB;
            pfxy[j] = xyp[q]; pfz[j] = zs2[q];
        }

        // locate smallest k with dist[k]==bv (descending serial; p monotone)
        int bp = 0;
#pragma unroll
        for (int k = PPT - 1; k >= 0; k--) {
            int p = 2 * (t + (k >> 1) * TPB) + (k & 1);
            if (dist[k] == bv) bp = p;
        }

        // warp-level exact argmax via two redux (hi = dist bits, lo = ~idx)
        unsigned khi = __float_as_uint(bv);
        unsigned klo = ~(unsigned)(base + bp);
        unsigned H, L;
        REDUX_MAX_U32(H, khi);
        unsigned cand = (khi == H) ? klo : 0u;
        REDUX_MAX_U32(L, cand);
        unsigned long long wkey = ((unsigned long long)H << 32) | L;

        // lanes 0-3: send warp candidate to rank=lane, arrive remote mbar
        {
            int off = (int)(~L) - base;           // in [0, PSH)
            if (lane < CPB) {
                float wx = xyf[(off >> 1) * 4 + (off & 1)];
                float wy = xyf[(off >> 1) * 4 + 2 + (off & 1)];
                float wz = zs[off];
                uint32_t kaddr = keys_base + (uint32_t)(par * NSLOT + slot) * 8u;
                uint32_t caddr = coord_base + (uint32_t)(par * NSLOT + slot) * 16u;
                uint32_t mb    = mbar_base + (uint32_t)par * 8u;
                uint32_t rk, rc, rm;
                asm("mapa.shared::cluster.u32 %0, %1, %2;" : "=r"(rk) : "r"(kaddr), "r"(lane));
                asm("mapa.shared::cluster.u32 %0, %1, %2;" : "=r"(rc) : "r"(caddr), "r"(lane));
                asm("mapa.shared::cluster.u32 %0, %1, %2;" : "=r"(rm) : "r"(mb),    "r"(lane));
                unsigned long long xy;
                PACK_F32X2(xy, __float_as_uint(wx), __float_as_uint(wy));
                asm volatile("st.shared::cluster.u64 [%0], %1;"
                             :: "r"(rk), "l"(wkey) : "memory");
                asm volatile("st.shared::cluster.u64 [%0], %1;"
                             :: "r"(rc), "l"(xy) : "memory");
                asm volatile("st.shared::cluster.u32 [%0+8], %1;"
                             :: "r"(rc), "r"(__float_as_uint(wz)) : "memory");
                asm volatile(
                    "mbarrier.arrive.release.cluster.shared::cluster.b64 _, [%0];"
                    :: "r"(rm) : "memory");
            }
        }

        // wait on LOCAL parity mbarrier (acquire, cluster scope) — hot poll
        {
            uint32_t mb = mbar_base + (uint32_t)par * 8u;
            uint32_t done;
            do {
                asm volatile(
                    "{\n\t.reg .pred p;\n\t"
                    "mbarrier.try_wait.parity.acquire.cluster.shared::cta.b64 p, [%1], %2;\n\t"
                    "selp.b32 %0, 1, 0, p;\n\t}"
                    : "=r"(done) : "r"(mb), "r"(ph) : "memory");
            } while (!done);
        }

        // every warp redundantly reduces the 64 candidates
        {
            const ulonglong2* kk2 = (const ulonglong2*)(keys + par * NSLOT);
            ulonglong2 kk = kk2[lane];            // slots 2*lane, 2*lane+1
            unsigned long long km = (kk.x > kk.y) ? kk.x : kk.y;
            unsigned hi = (unsigned)(km >> 32), lo = (unsigned)km;
            unsigned Hg, Lg;
            REDUX_MAX_U32(Hg, hi);
            unsigned cnd = (hi == Hg) ? lo : 0u;
            REDUX_MAX_U32(Lg, cnd);
            unsigned long long W = ((unsigned long long)Hg << 32) | Lg;
            unsigned bal = __ballot_sync(0xffffffffu, km == W);
            int src = __ffs(bal) - 1;
            int sidx2 = (kk.x == W) ? (2 * lane) : (2 * lane + 1);
            sidx2 = __shfl_sync(0xffffffffu, sidx2, src);
            float4 cc = coord[par * NSLOT + sidx2]; // broadcast LDS.128
            cx = cc.x; cy = cc.y; cz = cc.z;
            if (t == 0)
                sidx[iter + 1] = (int)(~Lg);        // local SMEM record
        }
    }

    // ---- fused gather: this CTA writes rows [c*128, (c+1)*128) of batch b
    __syncthreads();
    {
        const int ln = t & 15;                     // 16 threads per row
        float* out_f = out + (size_t)BATCH * SSAMP * 3;
#pragma unroll
        for (int pass = 0; pass < 4; pass++) {
            int r = pass * 32 + (t >> 4);          // 32 rows per pass
            int j = c * (SSAMP / CPB) + r;
            int idx = sidx[j];
            const float4* fr = (const float4*)(f + ((size_t)b * NPTS + idx) * 64);
            float4* fo = (float4*)(out_f + ((size_t)b * SSAMP + j) * 64);
            fo[ln] = fr[ln];
            if (ln < 3) {
                out[((size_t)b * SSAMP + j) * 3 + ln] =
                    xyz[((size_t)b * NPTS + idx) * 3 + ln];
            }
        }
    }
}

extern "C" void kernel_launch(void* const* d_in, const int* in_sizes, int n_in,
                              void* d_out, int out_size) {
    const float* xyz = (const float*)d_in[0];
    const float* f   = (const float*)d_in[1];
    float* out = (float*)d_out;

    size_t smem = (PSH / 2) * sizeof(ulonglong2)
                + PSH * sizeof(float)
                + 2 * NSLOT * sizeof(unsigned long long)
                + 2 * NSLOT * sizeof(float4)
                + 2 * sizeof(unsigned long long)
                + SSAMP * sizeof(int);
    cudaFuncSetAttribute(fps_kernel,
                         cudaFuncAttributeMaxDynamicSharedMemorySize, (int)smem);

    fps_kernel<<<BATCH * CPB, TPB, smem>>>(xyz, f, out);
}